// round 4
// baseline (speedup 1.0000x reference)
#include <cuda_runtime.h>
#include <math.h>
#include <stdint.h>

// ObjectosphereLoss: HBM-bound weighted-loss reduction.
//   inputs: logits[B,13] f32, true_y[B] (int32 or int64),
//           is_unknown[B] (uint8 or int32), deep_features[B,512] f32,
//           weights[13] f32
//   output: scalar f32 loss = sum(w*jr)/sum(w)
//
// R4 vs R3 (84.5us): single-launch. final_kernel (9.3us of pure launch/
// serialization overhead) replaced by fenced last-block reduction inside the
// main kernel. Deterministic: fixed-order reduce, counter order irrelevant;
// counter self-resets for graph replay.

#define DFEAT     512
#define NC        13
#define NBLK      2048
#define NTHR      256
#define WARPS_PER_BLK (NTHR / 32)

__device__ float g_pnum[NBLK];
__device__ float g_pden[NBLK];
__device__ unsigned int g_done = 0;

__global__ __launch_bounds__(NTHR)
void objectosphere_kernel(const float* __restrict__ logits,
                          const void*  __restrict__ ty,
                          const void*  __restrict__ unk,
                          const float* __restrict__ feat,
                          const float* __restrict__ weights,
                          float* __restrict__ out,
                          int nrows) {
    const int lane = threadIdx.x & 31;
    const int wid  = threadIdx.x >> 5;
    const int gw   = blockIdx.x * WARPS_PER_BLK + wid;
    const int tw   = gridDim.x * WARPS_PER_BLK;

    // ---- inline dtype detection (per-warp, parallel; L2-hot after wave 1) --
    // true_y int64: odd words 0, even words in [0,13). FP prob ~ 13^-32.
    int is64;
    {
        const int* t = (const int*)ty;
        int a = __ldg(t + lane), b = __ldg(t + lane + 32);
        int oka = (lane & 1) ? (a == 0) : (a >= 0 && a < NC);
        int okb = (lane & 1) ? (b == 0) : (b >= 0 && b < NC);
        is64 = (__ballot_sync(0xffffffffu, oka && okb) == 0xffffffffu);
    }
    // is_unknown int32: every word is 0/1. Packed-uint8 FP prob 2^-192.
    int is32;
    {
        const unsigned int* u = (const unsigned int*)unk;
        unsigned int a = __ldg(u + lane), b = __ldg(u + lane + 32);
        is32 = (__ballot_sync(0xffffffffu, (a <= 1u) && (b <= 1u))
                == 0xffffffffu);
    }

    float num = 0.f, den = 0.f;

    for (int row = gw; row < nrows; row += tw) {
        // ---- ||feature||^2: 4x float4 per lane, coalesced, streaming
        const float4* f = (const float4*)(feat + (size_t)row * DFEAT);
        float4 v0 = __ldcs(f + lane);
        float4 v1 = __ldcs(f + lane + 32);
        float4 v2 = __ldcs(f + lane + 64);
        float4 v3 = __ldcs(f + lane + 96);
        float ss = v0.x*v0.x + v0.y*v0.y + v0.z*v0.z + v0.w*v0.w;
        ss += v1.x*v1.x + v1.y*v1.y + v1.z*v1.z + v1.w*v1.w;
        ss += v2.x*v2.x + v2.y*v2.y + v2.z*v2.z + v2.w*v2.w;
        ss += v3.x*v3.x + v3.y*v3.y + v3.z*v3.z + v3.w*v3.w;
        #pragma unroll
        for (int o = 16; o > 0; o >>= 1)
            ss += __shfl_xor_sync(0xffffffffu, ss, o);

        // ---- softmax stats over 13 logits (no max-shift needed in f32)
        float l = (lane < NC) ? __ldg(logits + (size_t)row * NC + lane) : 0.f;
        float e = (lane < NC) ? __expf(l) : 0.f;
        float S = e, suml = l;
        #pragma unroll
        for (int o = 16; o > 0; o >>= 1) {
            S    += __shfl_xor_sync(0xffffffffu, S, o);
            suml += __shfl_xor_sync(0xffffffffu, suml, o);
        }
        float logS = __logf(S);

        // ---- label + mask (lane 0 loads, broadcast)
        int y = 0, uu = 0;
        if (lane == 0) {
            y  = is64 ? (int)((const long long*)ty)[row]
                      : ((const int*)ty)[row];
            uu = is32 ? (((const int*)unk)[row] != 0)
                      : (((const unsigned char*)unk)[row] != 0);
        }
        y  = __shfl_sync(0xffffffffu, y, 0);
        uu = __shfl_sync(0xffffffffu, uu, 0);
        float ly = __shfl_sync(0xffffffffu, l, y);

        float jr;
        if (uu) {
            jr = (13.f * logS - suml) * (1.f / 12.f) + 1e-4f * ss;
        } else {
            float h = fmaxf(10.f - sqrtf(ss), 0.f);
            jr = (logS - ly) + 1e-4f * h * h;
        }
        float w = __ldg(weights + y);
        num += w * jr;
        den += w;
    }

    // ---- block reduce ----
    __shared__ float sn[WARPS_PER_BLK], sd[WARPS_PER_BLK];
    if (lane == 0) { sn[wid] = num; sd[wid] = den; }
    __syncthreads();
    __shared__ int amLast;
    if (threadIdx.x == 0) {
        float a = 0.f, b = 0.f;
        #pragma unroll
        for (int i = 0; i < WARPS_PER_BLK; i++) { a += sn[i]; b += sd[i]; }
        g_pnum[blockIdx.x] = a;
        g_pden[blockIdx.x] = b;
        __threadfence();                                   // partials visible
        unsigned int prev = atomicAdd(&g_done, 1u);
        amLast = (prev == (unsigned)(gridDim.x - 1));
    }
    __syncthreads();

    // ---- fenced last-block final reduce (partials are L2-hot) ----
    if (amLast) {
        __shared__ double fn[NTHR], fd[NTHR];
        double a = 0.0, b = 0.0;
        for (int i = threadIdx.x; i < NBLK; i += NTHR) {
            a += (double)g_pnum[i];
            b += (double)g_pden[i];
        }
        fn[threadIdx.x] = a;
        fd[threadIdx.x] = b;
        __syncthreads();
        for (int s = NTHR / 2; s > 0; s >>= 1) {
            if (threadIdx.x < s) {
                fn[threadIdx.x] += fn[threadIdx.x + s];
                fd[threadIdx.x] += fd[threadIdx.x + s];
            }
            __syncthreads();
        }
        if (threadIdx.x == 0) {
            out[0] = (float)(fn[0] / fd[0]);
            g_done = 0;                    // reset for next graph replay
        }
    }
}

extern "C" void kernel_launch(void* const* d_in, const int* in_sizes, int n_in,
                              void* d_out, int out_size) {
    const float* logits  = (const float*)d_in[0];
    const void*  true_y  = d_in[1];
    const void*  is_unk  = d_in[2];
    const float* feat    = (const float*)d_in[3];
    const float* weights = (const float*)d_in[4];
    float* out = (float*)d_out;

    const int nrows = in_sizes[0] / NC;   // logits element count / 13

    objectosphere_kernel<<<NBLK, NTHR>>>(logits, true_y, is_unk, feat,
                                         weights, out, nrows);
}